// round 5
// baseline (speedup 1.0000x reference)
#include <cuda_runtime.h>
#include <cuda_bf16.h>
#include <cstdint>
#include <math.h>

#define BTOT 32768
#define KC 64
#define DD 64
#define LOG_2PI 1.8378770664093453f

// ---- persistent scratch ----
__device__ __nv_bfloat16 g_LinvBF[KC][DD * DD];  // [k][i*64+j] = Linv_k[i][j]
__device__ __nv_bfloat16 g_Db[KC * DD];          // [kc][j] = (Linv^T c)[j]
__device__ float    g_const2[KC];  // logw - hld - 0.5*D*log2pi - 0.5*||c||^2
__device__ double   g_partial[256];
__device__ unsigned g_cnt;

// ============================================================
// Kernel A: per-component preprocess + log-softmax (64 blocks x 64 thr)
// ============================================================
__global__ void prep_kernel(const float* __restrict__ means_raw,
                            const float* __restrict__ scale_raw,
                            const float* __restrict__ weights_raw) {
    const int k = blockIdx.x;
    const int t = threadIdx.x;
    __shared__ float L[DD][DD + 1];
    __shared__ float Y[DD][DD + 1];   // Y[j][i] = Linv[i][j] (column j)
    __shared__ float red[DD];
    __shared__ float mv[DD];
    __shared__ float cS[DD];
    const float g2 = 1.0f / 512.0f;
    const float g1 = 1.0f / 64.0f;

    if (k == 0 && t == 0) g_cnt = 0;   // reset completion counter each call

    // ---- log-softmax over all 64 weights (redundant per block, cheap) ----
    float v = weights_raw[t] * 0.125f;
    red[t] = v;
    __syncthreads();
    for (int s = 32; s > 0; s >>= 1) {
        if (t < s) red[t] = fmaxf(red[t], red[t + s]);
        __syncthreads();
    }
    float m = red[0];
    __syncthreads();
    red[t] = expf(v - m);
    __syncthreads();
    for (int s = 32; s > 0; s >>= 1) {
        if (t < s) red[t] += red[t + s];
        __syncthreads();
    }
    float lse = m + logf(red[0]);
    __syncthreads();

    for (int i = 0; i < DD; i++)
        L[i][t] = scale_raw[(k * DD + i) * DD + t] * g2;
    mv[t] = means_raw[k * DD + t] * g1;
    __syncthreads();

    red[t] = L[t][t];   // half_log_det = sum of pre-diagonal
    __syncthreads();
    for (int s = 32; s > 0; s >>= 1) {
        if (t < s) red[t] += red[t + s];
        __syncthreads();
    }
    float hld = red[0];
    __syncthreads();

    {   // row t of L: strict lower kept, exp on diag, zero above
        float dg = expf(L[t][t]);
        for (int j = t; j < DD; j++) L[t][j] = (j == t) ? dg : 0.0f;
    }
    __syncthreads();

    // forward substitution: column t of Linv
    for (int i = 0; i < t; i++) Y[t][i] = 0.0f;
    Y[t][t] = 1.0f / L[t][t];
    for (int i = t + 1; i < DD; i++) {
        float s = 0.0f;
        for (int mm = t; mm < i; mm++) s += L[i][mm] * Y[t][mm];
        Y[t][i] = -s / L[i][i];
    }
    __syncthreads();

    // c[t] = sum_{j<=t} Y[j][t] mu[j]
    float c = 0.0f;
    for (int j = 0; j <= t; j++) c += Y[j][t] * mv[j];
    cS[t] = c;
    __syncthreads();

    // d[t] = sum_i Y[t][i] cS[i]
    float d = 0.0f;
    for (int i = t; i < DD; i++) d += Y[t][i] * cS[i];
    g_Db[k * DD + t] = __float2bfloat16(d);

    // e = ||c||^2
    red[t] = c * c;
    __syncthreads();
    for (int s = 32; s > 0; s >>= 1) {
        if (t < s) red[t] += red[t + s];
        __syncthreads();
    }
    float e = red[0];

    // Linv bf16, row-major [i][j]; thread t owns column t
    for (int i = 0; i < DD; i++)
        g_LinvBF[k][i * DD + t] = __float2bfloat16(Y[t][i]);

    if (t == 0) {
        float vk = weights_raw[k] * 0.125f;
        g_const2[k] = (vk - lse) - hld - 0.5f * 64.0f * LOG_2PI - 0.5f * e;
    }
}

// ============================================================
// Main kernel: bf16 HMMA, A-frags hoisted, triple-buffered cp.async,
// fused deterministic final reduction. 256 CTAs x 128 thr.
// ============================================================
#define ROWB 144                        // 72 bf16 per smem row
#define XS_BYTES (128 * ROWB)           // 18432
#define LB_OFF   XS_BYTES
#define LB_BYTES (64 * ROWB)            // 9216 per buffer, x3
#define GS_OFF   (LB_OFF + 3 * LB_BYTES)        // 46080
#define GS_BYTES (128 * 65 * 4)                 // 33280
#define DSM_OFF  (GS_OFF + GS_BYTES)            // 79360
#define SMEM_TOTAL (DSM_OFF + 4 * 8)            // 79392

__device__ __forceinline__ void ldmx4(uint32_t a[4], uint32_t addr) {
    asm volatile("ldmatrix.sync.aligned.m8n8.x4.shared.b16 {%0,%1,%2,%3}, [%4];"
                 : "=r"(a[0]), "=r"(a[1]), "=r"(a[2]), "=r"(a[3]) : "r"(addr));
}
__device__ __forceinline__ void mma16816(float d[4], const uint32_t a[4],
                                         uint32_t b0, uint32_t b1) {
    asm volatile(
        "mma.sync.aligned.m16n8k16.row.col.f32.bf16.bf16.f32 "
        "{%0,%1,%2,%3}, {%4,%5,%6,%7}, {%8,%9}, {%0,%1,%2,%3};"
        : "+f"(d[0]), "+f"(d[1]), "+f"(d[2]), "+f"(d[3])
        : "r"(a[0]), "r"(a[1]), "r"(a[2]), "r"(a[3]), "r"(b0), "r"(b1));
}
__device__ __forceinline__ void cp_lb(uint32_t dstBase,
                                      const __nv_bfloat16* src, int t) {
#pragma unroll
    for (int q = 0; q < 4; q++) {
        int f = t + q * 128;            // 0..511 16B chunks
        uint32_t dst = dstBase + (f >> 3) * ROWB + (f & 7) * 16;
        asm volatile("cp.async.ca.shared.global [%0], [%1], 16;"
                     :: "r"(dst), "l"(src + f * 8));
    }
}

// acc(32x64) = Xwarp(32x64) * B(64x64)^T, A-frags preloaded
__device__ __forceinline__ void gemm_tile(float acc[2][8][4],
                                          const uint32_t afr[4][2][4],
                                          uint32_t LbB, int lr, int lc) {
#pragma unroll
    for (int ma = 0; ma < 2; ma++)
#pragma unroll
        for (int n8 = 0; n8 < 8; n8++)
#pragma unroll
            for (int q = 0; q < 4; q++) acc[ma][n8][q] = 0.0f;

#pragma unroll
    for (int ks = 0; ks < 4; ks++) {
        uint32_t b[8][2];
#pragma unroll
        for (int ng = 0; ng < 4; ng++) {
            uint32_t r[4];
            ldmx4(r, LbB + (ng * 16 + lr) * ROWB + ks * 32 + lc);
            b[2 * ng][0] = r[0]; b[2 * ng][1] = r[2];
            b[2 * ng + 1][0] = r[1]; b[2 * ng + 1][1] = r[3];
        }
#pragma unroll
        for (int ma = 0; ma < 2; ma++)
#pragma unroll
            for (int n8 = 0; n8 < 8; n8++)
                mma16816(acc[ma][n8], afr[ks][ma], b[n8][0], b[n8][1]);
    }
}

__global__ __launch_bounds__(128) void main_kernel(const float* __restrict__ x,
                                                   float* __restrict__ out) {
    extern __shared__ char smem[];
    __nv_bfloat16* Xs = (__nv_bfloat16*)smem;
    float* gS = (float*)(smem + GS_OFF);
    double* dsm = (double*)(smem + DSM_OFF);

    const int t = threadIdx.x;
    const int w = t >> 5, l = t & 31;
    const int m0w = w * 32;
    const int b0 = blockIdx.x * 128;
    uint32_t sbase = (uint32_t)__cvta_generic_to_shared(smem);
    uint32_t LbA = sbase + LB_OFF;
    uint32_t XsW = sbase + m0w * ROWB;
    const int lr = (l & 15);
    const int lc = (l >> 4) * 16;

    // ---- load X tile (128x64 f32) -> bf16 smem ----
    {
        const float4* X4 = (const float4*)(x + (size_t)b0 * 64);
#pragma unroll
        for (int q = 0; q < 16; q++) {
            int f = t + q * 128;
            int row = f >> 4, cq = f & 15;
            float4 v = X4[f];
            __nv_bfloat162 p0 = __float22bfloat162_rn(make_float2(v.x, v.y));
            __nv_bfloat162 p1 = __float22bfloat162_rn(make_float2(v.z, v.w));
            uint2 pk;
            pk.x = *reinterpret_cast<uint32_t*>(&p0);
            pk.y = *reinterpret_cast<uint32_t*>(&p1);
            *reinterpret_cast<uint2*>(&Xs[row * 72 + cq * 4]) = pk;
        }
    }

    // stage D (cross-term matrix) into slot 0
    cp_lb(LbA, g_Db, t);
    asm volatile("cp.async.commit_group;");
    asm volatile("cp.async.wait_group 0;");
    __syncthreads();   // X + D visible

    // ---- hoist A fragments (invariant across all components) ----
    uint32_t afr[4][2][4];
#pragma unroll
    for (int ks = 0; ks < 4; ks++)
#pragma unroll
        for (int ma = 0; ma < 2; ma++)
            ldmx4(afr[ks][ma], XsW + (ma * 16 + lr) * ROWB + ks * 32 + lc);

    float acc[2][8][4];

    // ---- G phase: G = X * D^T ----
    gemm_tile(acc, afr, LbA, lr, lc);
#pragma unroll
    for (int ma = 0; ma < 2; ma++)
#pragma unroll
        for (int n8 = 0; n8 < 8; n8++) {
            int row = m0w + ma * 16 + (l >> 2);
            int col = n8 * 8 + (l & 3) * 2;
            gS[row * 65 + col]           = acc[ma][n8][0];
            gS[row * 65 + col + 1]       = acc[ma][n8][1];
            gS[(row + 8) * 65 + col]     = acc[ma][n8][2];
            gS[(row + 8) * 65 + col + 1] = acc[ma][n8][3];
        }
    __syncthreads();   // gS visible; slot 0 free

    // ---- prologue: stage Linv[0] -> slot0, Linv[1] -> slot1 ----
    cp_lb(LbA, g_LinvBF[0], t);
    asm volatile("cp.async.commit_group;");
    cp_lb(LbA + LB_BYTES, g_LinvBF[1], t);
    asm volatile("cp.async.commit_group;");

    float runm[4], runs[4];
#pragma unroll
    for (int i = 0; i < 4; i++) { runm[i] = -INFINITY; runs[i] = 0.0f; }

    for (int k = 0; k < KC; k++) {
        asm volatile("cp.async.wait_group 1;");   // comp k resident
        __syncthreads();                          // + all reads of comp k-1 done

        // prefetch comp k+2 into slot (k+2)%3 (freed by comp k-1)
        if (k + 2 < KC) cp_lb(LbA + ((k + 2) % 3) * LB_BYTES, g_LinvBF[k + 2], t);
        asm volatile("cp.async.commit_group;");

        gemm_tile(acc, afr, LbA + (k % 3) * LB_BYTES, lr, lc);

        // sum of squares per row
        float p[4];
#pragma unroll
        for (int ma = 0; ma < 2; ma++) {
            float s0 = 0.0f, s1 = 0.0f;
#pragma unroll
            for (int n8 = 0; n8 < 8; n8++) {
                s0 = fmaf(acc[ma][n8][0], acc[ma][n8][0], s0);
                s0 = fmaf(acc[ma][n8][1], acc[ma][n8][1], s0);
                s1 = fmaf(acc[ma][n8][2], acc[ma][n8][2], s1);
                s1 = fmaf(acc[ma][n8][3], acc[ma][n8][3], s1);
            }
            p[ma * 2] = s0; p[ma * 2 + 1] = s1;
        }
#pragma unroll
        for (int off = 1; off <= 2; off <<= 1)
#pragma unroll
            for (int i = 0; i < 4; i++)
                p[i] += __shfl_xor_sync(0xffffffffu, p[i], off);

        if ((l & 3) == 0) {
            float c2 = g_const2[k];
#pragma unroll
            for (int i = 0; i < 4; i++) {
                int row = m0w + (i >> 1) * 16 + (i & 1) * 8 + (l >> 2);
                float g = gS[row * 65 + k];
                float s = c2 - 0.5f * p[i] + g;
                float nm = fmaxf(runm[i], s);
                runs[i] = runs[i] * __expf(runm[i] - nm) + __expf(s - nm);
                runm[i] = nm;
            }
        }
    }

    // ---- per-CTA deterministic reduction ----
    double lps = 0.0;
    if ((l & 3) == 0) {
#pragma unroll
        for (int i = 0; i < 4; i++)
            lps += (double)(runm[i] + logf(runs[i]));
    }
#pragma unroll
    for (int off = 16; off > 0; off >>= 1)
        lps += __shfl_xor_sync(0xffffffffu, lps, off);
    if (l == 0) dsm[w] = lps;
    __syncthreads();
    if (t == 0)
        g_partial[blockIdx.x] = dsm[0] + dsm[1] + dsm[2] + dsm[3];

    // ---- last-block final reduction (deterministic fixed-order tree) ----
    __shared__ bool isLast;
    __threadfence();
    if (t == 0) isLast = (atomicAdd(&g_cnt, 1u) == 255u);
    __syncthreads();
    if (isLast) {
        __threadfence();
        const volatile double* gp = (const volatile double*)g_partial;
        __shared__ double dd[128];
        dd[t] = gp[t] + gp[t + 128];
        __syncthreads();
        for (int s = 64; s > 0; s >>= 1) {
            if (t < s) dd[t] += dd[t + s];
            __syncthreads();
        }
        if (t == 0) out[0] = (float)(-dd[0] / (double)BTOT);
    }
}

// ============================================================
extern "C" void kernel_launch(void* const* d_in, const int* in_sizes, int n_in,
                              void* d_out, int out_size) {
    const float* x           = (const float*)d_in[0];
    const float* means_raw   = (const float*)d_in[1];
    const float* scale_raw   = (const float*)d_in[2];
    const float* weights_raw = (const float*)d_in[3];
    float* out = (float*)d_out;

    cudaFuncSetAttribute(main_kernel, cudaFuncAttributeMaxDynamicSharedMemorySize,
                         SMEM_TOTAL);

    prep_kernel<<<64, 64>>>(means_raw, scale_raw, weights_raw);
    main_kernel<<<256, 128, SMEM_TOTAL>>>(x, out);
}

// round 6
// speedup vs baseline: 1.0218x; 1.0218x over previous
#include <cuda_runtime.h>
#include <cuda_bf16.h>
#include <cstdint>
#include <math.h>

#define BTOT 32768
#define KC 64
#define DD 64
#define LOG_2PI 1.8378770664093453f

// ---- persistent scratch ----
__device__ __nv_bfloat16 g_LinvBF[KC][DD * DD];  // [k][i*64+j] = Linv_k[i][j]
__device__ __nv_bfloat16 g_Db[KC * DD];          // [kc][j] = (Linv^T c)[j]
__device__ float    g_const2[KC];  // logw - hld - 0.5*D*log2pi - 0.5*||c||^2
__device__ double   g_partial[256];
__device__ unsigned g_cnt;

// ============================================================
// Kernel A: preprocess, 64 blocks x 256 threads.
// Parallel column-sweep triangular inversion: 64 barrier steps,
// rank-1 update spread over 256 threads.
// ============================================================
__global__ __launch_bounds__(256) void prep_kernel(const float* __restrict__ means_raw,
                                                   const float* __restrict__ scale_raw,
                                                   const float* __restrict__ weights_raw) {
    const int k = blockIdx.x;
    const int t = threadIdx.x;
    __shared__ float L[DD][DD + 1];
    __shared__ float R[DD][DD + 1];   // becomes Linv (row-major)
    __shared__ float yrow[DD];
    __shared__ float rdiag[DD];
    __shared__ float aux[DD];
    __shared__ float aux2[DD];
    __shared__ float mv[DD];
    __shared__ float cS[DD];
    const float g2 = 1.0f / 512.0f;
    const float g1 = 1.0f / 64.0f;

    if (k == 0 && t == 0) g_cnt = 0;

    // load L (scaled) and zero R
    for (int idx = t; idx < DD * DD; idx += 256) {
        int i = idx >> 6, j = idx & 63;
        L[i][j] = scale_raw[k * DD * DD + idx] * g2;
        R[i][j] = 0.0f;
    }
    float v = 0.0f;
    if (t < 64) {
        mv[t] = means_raw[k * DD + t] * g1;
        v = weights_raw[t] * 0.125f;
        aux[t] = v;
    }
    __syncthreads();

    // ---- log-softmax denominator over 64 weights ----
    for (int s = 32; s > 0; s >>= 1) {
        if (t < s) aux[t] = fmaxf(aux[t], aux[t + s]);
        __syncthreads();
    }
    float m = aux[0];
    __syncthreads();
    if (t < 64) aux2[t] = expf(v - m);
    __syncthreads();
    for (int s = 32; s > 0; s >>= 1) {
        if (t < s) aux2[t] += aux2[t + s];
        __syncthreads();
    }
    float lse = m + logf(aux2[0]);
    __syncthreads();

    // ---- half_log_det = sum of pre-diagonal; set diag/exp; init R=I ----
    if (t < 64) aux[t] = L[t][t];
    __syncthreads();
    for (int s = 32; s > 0; s >>= 1) {
        if (t < s) aux[t] += aux[t + s];
        __syncthreads();
    }
    float hld = aux[0];
    __syncthreads();
    if (t < 64) {
        float dg = expf(L[t][t]);
        L[t][t] = dg;
        rdiag[t] = 1.0f / dg;
        R[t][t] = 1.0f;
    }
    __syncthreads();

    // ---- column-sweep forward substitution: R := Linv ----
    const int grp = t >> 6;        // 0..3 row groups
    const int col = t & 63;
    for (int i = 0; i < DD; i++) {
        if (t < 64) {
            float y = R[i][t] * rdiag[i];
            yrow[t] = y;
            R[i][t] = y;
        }
        __syncthreads();
        float y = yrow[col];
        for (int j = i + 1 + grp; j < DD; j += 4)
            R[j][col] -= L[j][i] * y;
        __syncthreads();
    }

    // ---- c[t] = sum_j Linv[t][j] mv[j] ----
    if (t < 64) {
        float c = 0.0f;
        for (int j = 0; j <= t; j++) c += R[t][j] * mv[j];
        cS[t] = c;
        aux[t] = c * c;
    }
    __syncthreads();
    // d[t] = sum_i Linv[i][t] cS[i]
    if (t < 64) {
        float d = 0.0f;
        for (int i = t; i < DD; i++) d += R[i][t] * cS[i];
        g_Db[k * DD + t] = __float2bfloat16(d);
    }
    for (int s = 32; s > 0; s >>= 1) {
        if (t < s) aux[t] += aux[t + s];
        __syncthreads();
    }
    float e = aux[0];

    // store Linv bf16 row-major
    for (int idx = t; idx < DD * DD; idx += 256) {
        int i = idx >> 6, j = idx & 63;
        g_LinvBF[k][idx] = __float2bfloat16(R[i][j]);
    }

    if (t == 0) {
        float vk = weights_raw[k] * 0.125f;
        g_const2[k] = (vk - lse) - hld - 0.5f * 64.0f * LOG_2PI - 0.5f * e;
    }
}

// ============================================================
// Main kernel: bf16 HMMA, 256 CTAs x 256 thr (8 warps, 2x2 warp
// tiling: warp = M32 x N32). A-frags hoisted, triple-buffered
// cp.async, fused deterministic final reduction.
// ============================================================
#define ROWB 144                        // 72 bf16 per smem row
#define XS_BYTES (128 * ROWB)           // 18432
#define LB_OFF   XS_BYTES
#define LB_BYTES (64 * ROWB)            // 9216 per buffer, x3
#define GS_OFF   (LB_OFF + 3 * LB_BYTES)        // 46080
#define GS_BYTES (128 * 65 * 4)                 // 33280
#define MAHA_OFF (GS_OFF + GS_BYTES)            // 79360
#define DSM_OFF  (MAHA_OFF + 128 * 4)           // 79872
#define SMEM_TOTAL (DSM_OFF + 4 * 8)            // 79904

__device__ __forceinline__ void ldmx4(uint32_t a[4], uint32_t addr) {
    asm volatile("ldmatrix.sync.aligned.m8n8.x4.shared.b16 {%0,%1,%2,%3}, [%4];"
                 : "=r"(a[0]), "=r"(a[1]), "=r"(a[2]), "=r"(a[3]) : "r"(addr));
}
__device__ __forceinline__ void mma16816(float d[4], const uint32_t a[4],
                                         uint32_t b0, uint32_t b1) {
    asm volatile(
        "mma.sync.aligned.m16n8k16.row.col.f32.bf16.bf16.f32 "
        "{%0,%1,%2,%3}, {%4,%5,%6,%7}, {%8,%9}, {%0,%1,%2,%3};"
        : "+f"(d[0]), "+f"(d[1]), "+f"(d[2]), "+f"(d[3])
        : "r"(a[0]), "r"(a[1]), "r"(a[2]), "r"(a[3]), "r"(b0), "r"(b1));
}
__device__ __forceinline__ void cp_lb(uint32_t dstBase,
                                      const __nv_bfloat16* src, int t) {
#pragma unroll
    for (int q = 0; q < 2; q++) {
        int f = t + q * 256;            // 0..511 16B chunks
        uint32_t dst = dstBase + (f >> 3) * ROWB + (f & 7) * 16;
        asm volatile("cp.async.ca.shared.global [%0], [%1], 16;"
                     :: "r"(dst), "l"(src + f * 8));
    }
}

// acc(32x32) = Xwarp(32x64) * Brows[bro..bro+31](32x64)^T
__device__ __forceinline__ void gemm_tile32(float acc[2][4][4],
                                            const uint32_t afr[4][2][4],
                                            uint32_t LbB, int lr, int lc, int bro) {
#pragma unroll
    for (int ma = 0; ma < 2; ma++)
#pragma unroll
        for (int n8 = 0; n8 < 4; n8++)
#pragma unroll
            for (int q = 0; q < 4; q++) acc[ma][n8][q] = 0.0f;

#pragma unroll
    for (int ks = 0; ks < 4; ks++) {
        uint32_t b[4][2];
#pragma unroll
        for (int ng = 0; ng < 2; ng++) {
            uint32_t r[4];
            ldmx4(r, LbB + (bro + ng * 16 + lr) * ROWB + ks * 32 + lc);
            b[2 * ng][0] = r[0]; b[2 * ng][1] = r[2];
            b[2 * ng + 1][0] = r[1]; b[2 * ng + 1][1] = r[3];
        }
#pragma unroll
        for (int ma = 0; ma < 2; ma++)
#pragma unroll
            for (int n8 = 0; n8 < 4; n8++)
                mma16816(acc[ma][n8], afr[ks][ma], b[n8][0], b[n8][1]);
    }
}

__global__ __launch_bounds__(256) void main_kernel(const float* __restrict__ x,
                                                   float* __restrict__ out) {
    extern __shared__ char smem[];
    __nv_bfloat16* Xs = (__nv_bfloat16*)smem;
    float* gS = (float*)(smem + GS_OFF);
    float* mahaP = (float*)(smem + MAHA_OFF);
    double* dsm = (double*)(smem + DSM_OFF);

    const int t = threadIdx.x;
    const int w = t >> 5, l = t & 31;
    const int wr = w >> 1;          // row group 0..3 (32 rows each)
    const int wc = w & 1;           // col group 0..1 (32 cols each)
    const int m0w = wr * 32;
    const int bro = wc * 32;        // B-row (output-dim / component) offset
    const int b0 = blockIdx.x * 128;
    uint32_t sbase = (uint32_t)__cvta_generic_to_shared(smem);
    uint32_t LbA = sbase + LB_OFF;
    uint32_t XsW = sbase + m0w * ROWB;
    const int lr = (l & 15);
    const int lc = (l >> 4) * 16;
    const bool own = ((l & 3) == 0);

    // ---- load X tile (128x64 f32) -> bf16 smem ----
    {
        const float4* X4 = (const float4*)(x + (size_t)b0 * 64);
#pragma unroll
        for (int q = 0; q < 8; q++) {
            int f = t + q * 256;
            int row = f >> 4, cq = f & 15;
            float4 vv = X4[f];
            __nv_bfloat162 p0 = __float22bfloat162_rn(make_float2(vv.x, vv.y));
            __nv_bfloat162 p1 = __float22bfloat162_rn(make_float2(vv.z, vv.w));
            uint2 pk;
            pk.x = *reinterpret_cast<uint32_t*>(&p0);
            pk.y = *reinterpret_cast<uint32_t*>(&p1);
            *reinterpret_cast<uint2*>(&Xs[row * 72 + cq * 4]) = pk;
        }
    }

    // stage D (cross-term matrix) into slot 0
    cp_lb(LbA, g_Db, t);
    asm volatile("cp.async.commit_group;");
    asm volatile("cp.async.wait_group 0;");
    __syncthreads();   // X + D visible

    // ---- hoist A fragments (invariant across all components) ----
    uint32_t afr[4][2][4];
#pragma unroll
    for (int ks = 0; ks < 4; ks++)
#pragma unroll
        for (int ma = 0; ma < 2; ma++)
            ldmx4(afr[ks][ma], XsW + (ma * 16 + lr) * ROWB + ks * 32 + lc);

    float acc[2][4][4];

    // ---- G phase: G = X * D^T (this warp: comps bro..bro+31) ----
    gemm_tile32(acc, afr, LbA, lr, lc, bro);
#pragma unroll
    for (int ma = 0; ma < 2; ma++)
#pragma unroll
        for (int n8 = 0; n8 < 4; n8++) {
            int row = m0w + ma * 16 + (l >> 2);
            int col = bro + n8 * 8 + (l & 3) * 2;
            gS[row * 65 + col]           = acc[ma][n8][0];
            gS[row * 65 + col + 1]       = acc[ma][n8][1];
            gS[(row + 8) * 65 + col]     = acc[ma][n8][2];
            gS[(row + 8) * 65 + col + 1] = acc[ma][n8][3];
        }
    __syncthreads();   // gS visible; slot 0 free

    // ---- prologue: stage Linv[0] -> slot0, Linv[1] -> slot1 ----
    cp_lb(LbA, g_LinvBF[0], t);
    asm volatile("cp.async.commit_group;");
    cp_lb(LbA + LB_BYTES, g_LinvBF[1], t);
    asm volatile("cp.async.commit_group;");

    float runm[4], runs[4];
#pragma unroll
    for (int i = 0; i < 4; i++) { runm[i] = -INFINITY; runs[i] = 0.0f; }

    for (int k = 0; k < KC; k++) {
        asm volatile("cp.async.wait_group 1;");   // comp k resident
        __syncthreads();                          // + mahaP(k-1) consumed, slot free

        if (k + 2 < KC) cp_lb(LbA + ((k + 2) % 3) * LB_BYTES, g_LinvBF[k + 2], t);
        asm volatile("cp.async.commit_group;");

        gemm_tile32(acc, afr, LbA + (k % 3) * LB_BYTES, lr, lc, bro);

        // partial sum of squares over this warp's 32 dims
        float p[4];
#pragma unroll
        for (int ma = 0; ma < 2; ma++) {
            float s0 = 0.0f, s1 = 0.0f;
#pragma unroll
            for (int n8 = 0; n8 < 4; n8++) {
                s0 = fmaf(acc[ma][n8][0], acc[ma][n8][0], s0);
                s0 = fmaf(acc[ma][n8][1], acc[ma][n8][1], s0);
                s1 = fmaf(acc[ma][n8][2], acc[ma][n8][2], s1);
                s1 = fmaf(acc[ma][n8][3], acc[ma][n8][3], s1);
            }
            p[ma * 2] = s0; p[ma * 2 + 1] = s1;
        }
#pragma unroll
        for (int off = 1; off <= 2; off <<= 1)
#pragma unroll
            for (int i = 0; i < 4; i++)
                p[i] += __shfl_xor_sync(0xffffffffu, p[i], off);

        if (wc == 1 && own) {
#pragma unroll
            for (int i = 0; i < 4; i++) {
                int r = m0w + (i >> 1) * 16 + (i & 1) * 8 + (l >> 2);
                mahaP[r] = p[i];
            }
        }
        __syncthreads();   // mahaP(k) visible

        if (wc == 0 && own) {
            float c2 = g_const2[k];
#pragma unroll
            for (int i = 0; i < 4; i++) {
                int r = m0w + (i >> 1) * 16 + (i & 1) * 8 + (l >> 2);
                float tot = p[i] + mahaP[r];
                float s = c2 - 0.5f * tot + gS[r * 65 + k];
                float nm = fmaxf(runm[i], s);
                runs[i] = runs[i] * __expf(runm[i] - nm) + __expf(s - nm);
                runm[i] = nm;
            }
        }
    }

    // ---- per-CTA deterministic reduction ----
    double lps = 0.0;
    if (wc == 0 && own) {
#pragma unroll
        for (int i = 0; i < 4; i++)
            lps += (double)(runm[i] + logf(runs[i]));
    }
#pragma unroll
    for (int off = 16; off > 0; off >>= 1)
        lps += __shfl_xor_sync(0xffffffffu, lps, off);
    if (wc == 0 && l == 0) dsm[wr] = lps;
    __syncthreads();
    if (t == 0)
        g_partial[blockIdx.x] = dsm[0] + dsm[1] + dsm[2] + dsm[3];

    // ---- last-block final reduction (deterministic fixed-order tree) ----
    __shared__ bool isLast;
    __threadfence();
    if (t == 0) isLast = (atomicAdd(&g_cnt, 1u) == 255u);
    __syncthreads();
    if (isLast) {
        __threadfence();
        const volatile double* gp = (const volatile double*)g_partial;
        __shared__ double dd[256];
        dd[t] = gp[t];
        __syncthreads();
        for (int s = 128; s > 0; s >>= 1) {
            if (t < s) dd[t] += dd[t + s];
            __syncthreads();
        }
        if (t == 0) out[0] = (float)(-dd[0] / (double)BTOT);
    }
}

// ============================================================
extern "C" void kernel_launch(void* const* d_in, const int* in_sizes, int n_in,
                              void* d_out, int out_size) {
    const float* x           = (const float*)d_in[0];
    const float* means_raw   = (const float*)d_in[1];
    const float* scale_raw   = (const float*)d_in[2];
    const float* weights_raw = (const float*)d_in[3];
    float* out = (float*)d_out;

    cudaFuncSetAttribute(main_kernel, cudaFuncAttributeMaxDynamicSharedMemorySize,
                         SMEM_TOTAL);

    prep_kernel<<<64, 256>>>(means_raw, scale_raw, weights_raw);
    main_kernel<<<256, 256, SMEM_TOTAL>>>(x, out);
}

// round 7
// speedup vs baseline: 1.1304x; 1.1062x over previous
#include <cuda_runtime.h>
#include <cuda_bf16.h>
#include <cstdint>
#include <math.h>

#define BTOT 32768
#define KC 64
#define DD 64
#define LOG_2PI 1.8378770664093453f

// ---- persistent scratch ----
__device__ __nv_bfloat16 g_LinvBF[KC][DD * DD];  // [k][i*64+j] = Linv_k[i][j] (lower-tri)
__device__ __nv_bfloat16 g_Db[KC * DD];          // [kc][j] = (Linv^T c)[j] (dense)
__device__ float    g_const2[KC];  // logw - hld - 0.5*D*log2pi - 0.5*||c||^2
__device__ double   g_partial[256];
__device__ unsigned g_cnt;

// ============================================================
// Kernel A: preprocess, 64 blocks x 256 threads.
// Column-sweep inversion with fixed-trip unrolled predicated
// updates (16 rows/thread) so LDS ops pipeline.
// ============================================================
__global__ __launch_bounds__(256) void prep_kernel(const float* __restrict__ means_raw,
                                                   const float* __restrict__ scale_raw,
                                                   const float* __restrict__ weights_raw) {
    const int k = blockIdx.x;
    const int t = threadIdx.x;
    __shared__ float L[DD][DD + 1];
    __shared__ float R[DD][DD + 1];   // becomes Linv (row-major)
    __shared__ float yrow[DD];
    __shared__ float rdiag[DD];
    __shared__ float aux[DD];
    __shared__ float aux2[DD];
    __shared__ float mv[DD];
    __shared__ float cS[DD];
    const float g2 = 1.0f / 512.0f;
    const float g1 = 1.0f / 64.0f;

    if (k == 0 && t == 0) g_cnt = 0;

    for (int idx = t; idx < DD * DD; idx += 256) {
        int i = idx >> 6, j = idx & 63;
        L[i][j] = scale_raw[k * DD * DD + idx] * g2;
        R[i][j] = 0.0f;
    }
    float v = 0.0f;
    if (t < 64) {
        mv[t] = means_raw[k * DD + t] * g1;
        v = weights_raw[t] * 0.125f;
        aux[t] = v;
    }
    __syncthreads();

    // log-softmax denominator
    for (int s = 32; s > 0; s >>= 1) {
        if (t < s) aux[t] = fmaxf(aux[t], aux[t + s]);
        __syncthreads();
    }
    float m = aux[0];
    __syncthreads();
    if (t < 64) aux2[t] = expf(v - m);
    __syncthreads();
    for (int s = 32; s > 0; s >>= 1) {
        if (t < s) aux2[t] += aux2[t + s];
        __syncthreads();
    }
    float lse = m + logf(aux2[0]);
    __syncthreads();

    // half_log_det; diag exp; R = I
    if (t < 64) aux[t] = L[t][t];
    __syncthreads();
    for (int s = 32; s > 0; s >>= 1) {
        if (t < s) aux[t] += aux[t + s];
        __syncthreads();
    }
    float hld = aux[0];
    __syncthreads();
    if (t < 64) {
        float dg = expf(L[t][t]);
        L[t][t] = dg;
        rdiag[t] = 1.0f / dg;
        R[t][t] = 1.0f;
    }
    __syncthreads();

    // column-sweep forward substitution, unrolled fixed-trip updates
    const int rb = (t >> 6) * 16;   // 16-row block per thread group
    const int col = t & 63;
    for (int i = 0; i < DD; i++) {
        if (t < 64) {
            float y = R[i][t] * rdiag[i];
            yrow[t] = y;
            R[i][t] = y;
        }
        __syncthreads();
        float y = yrow[col];
#pragma unroll
        for (int jj = 0; jj < 16; jj++) {
            int j = rb + jj;
            if (j > i) R[j][col] = fmaf(-L[j][i], y, R[j][col]);
        }
        __syncthreads();
    }

    if (t < 64) {
        float c = 0.0f;
        for (int j = 0; j <= t; j++) c += R[t][j] * mv[j];
        cS[t] = c;
        aux[t] = c * c;
    }
    __syncthreads();
    if (t < 64) {
        float d = 0.0f;
        for (int i = t; i < DD; i++) d += R[i][t] * cS[i];
        g_Db[k * DD + t] = __float2bfloat16(d);
    }
    for (int s = 32; s > 0; s >>= 1) {
        if (t < s) aux[t] += aux[t + s];
        __syncthreads();
    }
    float e = aux[0];

    for (int idx = t; idx < DD * DD; idx += 256) {
        int i = idx >> 6, j = idx & 63;
        g_LinvBF[k][idx] = __float2bfloat16(R[i][j]);
    }

    if (t == 0) {
        float vk = weights_raw[k] * 0.125f;
        g_const2[k] = (vk - lse) - hld - 0.5f * 64.0f * LOG_2PI - 0.5f * e;
    }
}

// ============================================================
// Main kernel: bf16 HMMA, 256 CTAs x 128 thr (4 warps, warp tile
// M32xN64). Triangular skip (-25% HMMA/LDSM), 6-slot B ring with
// groups of 3 comps per barrier pair, hoisted A-frags, fused
// deterministic final reduction.
// ============================================================
#define ROWB 144                        // 72 bf16 per smem row
#define XS_BYTES (128 * ROWB)           // 18432
#define LB_OFF   XS_BYTES
#define LB_BYTES (64 * ROWB)            // 9216 per slot
#define NSLOT 6
#define GS_OFF   (LB_OFF + NSLOT * LB_BYTES)    // 73728
#define GS_BYTES (128 * 65 * 4)                 // 33280
#define DSM_OFF  (GS_OFF + GS_BYTES)            // 107008
#define SMEM_TOTAL (DSM_OFF + 4 * 8)            // 107040

__device__ __forceinline__ void ldmx4(uint32_t a[4], uint32_t addr) {
    asm volatile("ldmatrix.sync.aligned.m8n8.x4.shared.b16 {%0,%1,%2,%3}, [%4];"
                 : "=r"(a[0]), "=r"(a[1]), "=r"(a[2]), "=r"(a[3]) : "r"(addr));
}
__device__ __forceinline__ void mma16816(float d[4], const uint32_t a[4],
                                         uint32_t b0, uint32_t b1) {
    asm volatile(
        "mma.sync.aligned.m16n8k16.row.col.f32.bf16.bf16.f32 "
        "{%0,%1,%2,%3}, {%4,%5,%6,%7}, {%8,%9}, {%0,%1,%2,%3};"
        : "+f"(d[0]), "+f"(d[1]), "+f"(d[2]), "+f"(d[3])
        : "r"(a[0]), "r"(a[1]), "r"(a[2]), "r"(a[3]), "r"(b0), "r"(b1));
}
__device__ __forceinline__ void cp_lb(uint32_t dstBase,
                                      const __nv_bfloat16* src, int t) {
#pragma unroll
    for (int q = 0; q < 4; q++) {
        int f = t + q * 128;            // 0..511 16B chunks
        uint32_t dst = dstBase + (f >> 3) * ROWB + (f & 7) * 16;
        asm volatile("cp.async.ca.shared.global [%0], [%1], 16;"
                     :: "r"(dst), "l"(src + f * 8));
    }
}

// acc(32x64) = Xwarp(32x64) * B(64x64)^T.
// TRI: B lower-triangular -> rows<32 need only K<32 (skip ks>=2, ng<2 / n8<4).
template <bool TRI>
__device__ __forceinline__ void gemm_tile(float acc[2][8][4],
                                          const uint32_t afr[4][2][4],
                                          uint32_t LbB, int lr, int lc) {
#pragma unroll
    for (int ma = 0; ma < 2; ma++)
#pragma unroll
        for (int n8 = 0; n8 < 8; n8++)
#pragma unroll
            for (int q = 0; q < 4; q++) acc[ma][n8][q] = 0.0f;

#pragma unroll
    for (int ks = 0; ks < 4; ks++) {
        uint32_t b[8][2];
#pragma unroll
        for (int ng = 0; ng < 4; ng++) {
            if (TRI && ks >= 2 && ng < 2) continue;
            uint32_t r[4];
            ldmx4(r, LbB + (ng * 16 + lr) * ROWB + ks * 32 + lc);
            b[2 * ng][0] = r[0]; b[2 * ng][1] = r[2];
            b[2 * ng + 1][0] = r[1]; b[2 * ng + 1][1] = r[3];
        }
#pragma unroll
        for (int ma = 0; ma < 2; ma++)
#pragma unroll
            for (int n8 = 0; n8 < 8; n8++) {
                if (TRI && ks >= 2 && n8 < 4) continue;
                mma16816(acc[ma][n8], afr[ks][ma], b[n8][0], b[n8][1]);
            }
    }
}

__global__ __launch_bounds__(128) void main_kernel(const float* __restrict__ x,
                                                   float* __restrict__ out) {
    extern __shared__ char smem[];
    __nv_bfloat16* Xs = (__nv_bfloat16*)smem;
    float* gS = (float*)(smem + GS_OFF);
    double* dsm = (double*)(smem + DSM_OFF);

    const int t = threadIdx.x;
    const int w = t >> 5, l = t & 31;
    const int m0w = w * 32;
    const int b0 = blockIdx.x * 128;
    uint32_t sbase = (uint32_t)__cvta_generic_to_shared(smem);
    uint32_t LbA = sbase + LB_OFF;
    uint32_t XsW = sbase + m0w * ROWB;
    const int lr = (l & 15);
    const int lc = (l >> 4) * 16;
    const bool own = ((l & 3) == 0);

    // ---- load X tile (128x64 f32) -> bf16 smem ----
    {
        const float4* X4 = (const float4*)(x + (size_t)b0 * 64);
#pragma unroll
        for (int q = 0; q < 16; q++) {
            int f = t + q * 128;
            int row = f >> 4, cq = f & 15;
            float4 vv = X4[f];
            __nv_bfloat162 p0 = __float22bfloat162_rn(make_float2(vv.x, vv.y));
            __nv_bfloat162 p1 = __float22bfloat162_rn(make_float2(vv.z, vv.w));
            uint2 pk;
            pk.x = *reinterpret_cast<uint32_t*>(&p0);
            pk.y = *reinterpret_cast<uint32_t*>(&p1);
            *reinterpret_cast<uint2*>(&Xs[row * 72 + cq * 4]) = pk;
        }
    }

    // stage D (dense cross-term matrix) into slot 0   [commit group #0]
    cp_lb(LbA, g_Db, t);
    asm volatile("cp.async.commit_group;");
    asm volatile("cp.async.wait_group 0;");
    __syncthreads();   // X + D visible

    // ---- hoist A fragments ----
    uint32_t afr[4][2][4];
#pragma unroll
    for (int ks = 0; ks < 4; ks++)
#pragma unroll
        for (int ma = 0; ma < 2; ma++)
            ldmx4(afr[ks][ma], XsW + (ma * 16 + lr) * ROWB + ks * 32 + lc);

    float acc[2][8][4];

    // ---- G phase: G = X * D^T (dense) ----
    gemm_tile<false>(acc, afr, LbA, lr, lc);
#pragma unroll
    for (int ma = 0; ma < 2; ma++)
#pragma unroll
        for (int n8 = 0; n8 < 8; n8++) {
            int row = m0w + ma * 16 + (l >> 2);
            int col = n8 * 8 + (l & 3) * 2;
            gS[row * 65 + col]           = acc[ma][n8][0];
            gS[row * 65 + col + 1]       = acc[ma][n8][1];
            gS[(row + 8) * 65 + col]     = acc[ma][n8][2];
            gS[(row + 8) * 65 + col + 1] = acc[ma][n8][3];
        }
    __syncthreads();   // gS visible; slot 0 free

    // ---- prologue: stage comps 0..5 into slots 0..5  [groups #1..#6] ----
#pragma unroll
    for (int k = 0; k < NSLOT; k++) {
        cp_lb(LbA + k * LB_BYTES, g_LinvBF[k], t);
        asm volatile("cp.async.commit_group;");
    }

    float runm[4], runs[4];
#pragma unroll
    for (int i = 0; i < 4; i++) { runm[i] = -INFINITY; runs[i] = 0.0f; }

    // groups of 3 comps: 2 barriers / 3 comps
    for (int g = 0; g < KC; g += 3) {
        asm volatile("cp.async.wait_group 3;");   // comps g..g+2 resident
        __syncthreads();                          // visible to all warps

#pragma unroll
        for (int kk = 0; kk < 3; kk++) {
            const int k = g + kk;
            if (k >= KC) break;
            gemm_tile<true>(acc, afr, LbA + (k % NSLOT) * LB_BYTES, lr, lc);

            float p[4];
#pragma unroll
            for (int ma = 0; ma < 2; ma++) {
                float s0 = 0.0f, s1 = 0.0f;
#pragma unroll
                for (int n8 = 0; n8 < 8; n8++) {
                    s0 = fmaf(acc[ma][n8][0], acc[ma][n8][0], s0);
                    s0 = fmaf(acc[ma][n8][1], acc[ma][n8][1], s0);
                    s1 = fmaf(acc[ma][n8][2], acc[ma][n8][2], s1);
                    s1 = fmaf(acc[ma][n8][3], acc[ma][n8][3], s1);
                }
                p[ma * 2] = s0; p[ma * 2 + 1] = s1;
            }
#pragma unroll
            for (int off = 1; off <= 2; off <<= 1)
#pragma unroll
                for (int i = 0; i < 4; i++)
                    p[i] += __shfl_xor_sync(0xffffffffu, p[i], off);

            if (own) {
                float c2 = g_const2[k];
#pragma unroll
                for (int i = 0; i < 4; i++) {
                    int r = m0w + (i >> 1) * 16 + (i & 1) * 8 + (l >> 2);
                    float s = c2 - 0.5f * p[i] + gS[r * 65 + k];
                    float nm = fmaxf(runm[i], s);
                    runs[i] = runs[i] * __expf(runm[i] - nm) + __expf(s - nm);
                    runm[i] = nm;
                }
            }
        }

        __syncthreads();   // all warps done reading slots g..g+2
        // prefetch comps g+6..g+8 into freed slots; commit ALWAYS (uniform counts)
#pragma unroll
        for (int kk = 0; kk < 3; kk++) {
            const int kp = g + NSLOT + kk;
            if (kp < KC) cp_lb(LbA + (kp % NSLOT) * LB_BYTES, g_LinvBF[kp], t);
            asm volatile("cp.async.commit_group;");
        }
    }

    // ---- per-CTA deterministic reduction ----
    double lps = 0.0;
    if (own) {
#pragma unroll
        for (int i = 0; i < 4; i++)
            lps += (double)(runm[i] + logf(runs[i]));
    }
#pragma unroll
    for (int off = 16; off > 0; off >>= 1)
        lps += __shfl_xor_sync(0xffffffffu, lps, off);
    if (l == 0) dsm[w] = lps;
    __syncthreads();
    if (t == 0)
        g_partial[blockIdx.x] = dsm[0] + dsm[1] + dsm[2] + dsm[3];

    // ---- last-block final reduction ----
    __shared__ bool isLast;
    __threadfence();
    if (t == 0) isLast = (atomicAdd(&g_cnt, 1u) == 255u);
    __syncthreads();
    if (isLast) {
        __threadfence();
        const volatile double* gp = (const volatile double*)g_partial;
        __shared__ double dd[128];
        dd[t] = gp[t] + gp[t + 128];
        __syncthreads();
        for (int s = 64; s > 0; s >>= 1) {
            if (t < s) dd[t] += dd[t + s];
            __syncthreads();
        }
        if (t == 0) out[0] = (float)(-dd[0] / (double)BTOT);
    }
}

// ============================================================
extern "C" void kernel_launch(void* const* d_in, const int* in_sizes, int n_in,
                              void* d_out, int out_size) {
    const float* x           = (const float*)d_in[0];
    const float* means_raw   = (const float*)d_in[1];
    const float* scale_raw   = (const float*)d_in[2];
    const float* weights_raw = (const float*)d_in[3];
    float* out = (float*)d_out;

    cudaFuncSetAttribute(main_kernel, cudaFuncAttributeMaxDynamicSharedMemorySize,
                         SMEM_TOTAL);

    prep_kernel<<<64, 256>>>(means_raw, scale_raw, weights_raw);
    main_kernel<<<256, 128, SMEM_TOTAL>>>(x, out);
}

// round 9
// speedup vs baseline: 1.3914x; 1.2310x over previous
#include <cuda_runtime.h>
#include <cuda_bf16.h>
#include <cstdint>
#include <math.h>

#define BTOT 32768
#define KC 64
#define DD 64
#define LOG_2PI 1.8378770664093453f

// ---- persistent scratch ----
__device__ __nv_bfloat16 g_LinvBF[KC][DD * DD];  // [k][i*64+j] (lower-tri, upper=0)
__device__ float    g_Cvec[KC][DD];              // c_k[i] = (Linv mu)[i], fp32
__device__ float    g_const2[KC];  // logw - hld - 0.5*D*log2pi
__device__ double   g_partial[256];
__device__ unsigned g_cnt;

// ============================================================
// Kernel A: preprocess, 64 blocks x 256 threads (8 warps).
// Warp-register column solver: warp w owns columns w*8..w*8+7,
// partial sums + results in registers, no block barriers in sweep.
// ============================================================
__global__ __launch_bounds__(256) void prep_kernel(const float* __restrict__ means_raw,
                                                   const float* __restrict__ scale_raw,
                                                   const float* __restrict__ weights_raw) {
    const int k = blockIdx.x;
    const int t = threadIdx.x;
    const int w = t >> 5, l = t & 31;
    __shared__ float Lp[DD][DD + 1];   // strictly-lower of L (else 0)
    __shared__ float R[DD][DD + 1];    // Linv (row-major), upper = 0
    __shared__ float dg[DD];           // raw diag (pre, before exp)
    __shared__ float aux[DD];
    __shared__ float aux2[DD];
    __shared__ float mv[DD];
    const float g2 = 1.0f / 512.0f;
    const float g1 = 1.0f / 64.0f;

    if (k == 0 && t == 0) g_cnt = 0;

    // load strictly-lower L (scaled); capture raw diag
    for (int idx = t; idx < DD * DD; idx += 256) {
        int i = idx >> 6, j = idx & 63;
        float raw = scale_raw[k * DD * DD + idx] * g2;
        Lp[i][j] = (i > j) ? raw : 0.0f;
        if (i == j) dg[i] = raw;
    }
    float v = 0.0f;
    if (t < 64) {
        mv[t] = means_raw[k * DD + t] * g1;
        v = weights_raw[t] * 0.125f;
        aux[t] = v;
    }
    __syncthreads();

    // log-softmax denominator over 64 weights
    for (int s = 32; s > 0; s >>= 1) {
        if (t < s) aux[t] = fmaxf(aux[t], aux[t + s]);
        __syncthreads();
    }
    float m = aux[0];
    __syncthreads();
    if (t < 64) { aux2[t] = expf(v - m); aux[t] = dg[t]; }
    __syncthreads();
    for (int s = 32; s > 0; s >>= 1) {
        if (t < s) { aux2[t] += aux2[t + s]; aux[t] += aux[t + s]; }
        __syncthreads();
    }
    float lse = m + logf(aux2[0]);
    float hld = aux[0];                 // half_log_det = sum of raw diag

    // ---- register column solver ----
    // lane l holds rows l (lo) and l+32 (hi); rdiag = 1/exp(diag) = exp(-diag)
    float rd0 = __expf(-dg[l]);
    float rd1 = __expf(-dg[l + 32]);
    float p0[8], p1[8], y0[8], y1[8];
#pragma unroll
    for (int j = 0; j < 8; j++) { p0[j] = p1[j] = y0[j] = y1[j] = 0.0f; }
    const int cbase = w * 8;

    for (int i = 0; i < DD; i++) {
        float Llo = Lp[l][i];
        float Lhi = Lp[l + 32][i];
        const int own = i & 31;
        const int half = i >> 5;
        float rdo = half ? rd1 : rd0;
#pragma unroll
        for (int j = 0; j < 8; j++) {
            const int c = cbase + j;
            float pown = half ? p1[j] : p0[j];
            float cv = ((i == c) ? 1.0f : 0.0f) - pown;
            cv *= rdo;
            float yb = __shfl_sync(0xffffffffu, cv, own);
            yb = (i >= c) ? yb : 0.0f;
            if (l == own) { if (half) y1[j] = yb; else y0[j] = yb; }
            p0[j] = fmaf(Llo, yb, p0[j]);
            p1[j] = fmaf(Lhi, yb, p1[j]);
        }
    }

    // write R (fp32): R[row][col]
#pragma unroll
    for (int j = 0; j < 8; j++) {
        R[l][cbase + j]      = y0[j];
        R[l + 32][cbase + j] = y1[j];
    }
    __syncthreads();

    // c[t] = sum_{j<=t} Linv[t][j] * mv[j]
    if (t < 64) {
        float c = 0.0f;
        for (int j = 0; j <= t; j++) c += R[t][j] * mv[j];
        g_Cvec[k][t] = c;
    }

    // store Linv bf16 (upper already 0 in R)
    for (int idx = t; idx < DD * DD; idx += 256) {
        int i = idx >> 6, j = idx & 63;
        g_LinvBF[k][idx] = __float2bfloat16(R[i][j]);
    }

    if (t == 0) {
        float vk = weights_raw[k] * 0.125f;
        g_const2[k] = (vk - lse) - hld - 0.5f * 64.0f * LOG_2PI;
    }
}

// ============================================================
// Main kernel: bf16 HMMA, 256 CTAs x 128 thr (4 warps, M32xN64),
// acc initialized to -c_k (z = Linv x - c directly), triangular
// skip, 6-slot ring (3 comps / barrier pair), ~75KB smem -> 3 CTAs/SM.
// ============================================================
#define ROWB 144                        // 72 bf16 per smem row
#define XS_BYTES (128 * ROWB)           // 18432
#define LB_OFF   XS_BYTES
#define LB_BYTES (64 * ROWB)            // 9216 per slot
#define NSLOT 6
#define CV_OFF   (LB_OFF + NSLOT * LB_BYTES)    // 73728
#define CV_BYTES (NSLOT * 64 * 4)               // 1536
#define DSM_OFF  (CV_OFF + CV_BYTES)            // 75264
#define SMEM_TOTAL (DSM_OFF + 4 * 8)            // 75296

__device__ __forceinline__ void ldmx4(uint32_t a[4], uint32_t addr) {
    asm volatile("ldmatrix.sync.aligned.m8n8.x4.shared.b16 {%0,%1,%2,%3}, [%4];"
                 : "=r"(a[0]), "=r"(a[1]), "=r"(a[2]), "=r"(a[3]) : "r"(addr));
}
__device__ __forceinline__ void mma16816(float d[4], const uint32_t a[4],
                                         uint32_t b0, uint32_t b1) {
    asm volatile(
        "mma.sync.aligned.m16n8k16.row.col.f32.bf16.bf16.f32 "
        "{%0,%1,%2,%3}, {%4,%5,%6,%7}, {%8,%9}, {%0,%1,%2,%3};"
        : "+f"(d[0]), "+f"(d[1]), "+f"(d[2]), "+f"(d[3])
        : "r"(a[0]), "r"(a[1]), "r"(a[2]), "r"(a[3]), "r"(b0), "r"(b1));
}
// stage Linv[comp] into slot + its c vector (256B)
__device__ __forceinline__ void cp_slot(uint32_t LbA, uint32_t CvA, int slot,
                                        int comp, int t) {
    uint32_t dstB = LbA + slot * LB_BYTES;
    const __nv_bfloat16* src = g_LinvBF[comp];
#pragma unroll
    for (int q = 0; q < 4; q++) {
        int f = t + q * 128;            // 0..511 16B chunks
        uint32_t dst = dstB + (f >> 3) * ROWB + (f & 7) * 16;
        asm volatile("cp.async.ca.shared.global [%0], [%1], 16;"
                     :: "r"(dst), "l"(src + f * 8));
    }
    if (t < 16) {
        uint32_t dst = CvA + slot * 256 + t * 16;
        asm volatile("cp.async.ca.shared.global [%0], [%1], 16;"
                     :: "r"(dst), "l"(&g_Cvec[comp][t * 4]));
    }
}

// acc(32x64) = -c + Xwarp(32x64) * B(64x64)^T, B lower-triangular
__device__ __forceinline__ void gemm_tile(float acc[2][8][4],
                                          const uint32_t afr[4][2][4],
                                          uint32_t LbB, const float2 ci[8],
                                          int lr, int lc) {
#pragma unroll
    for (int n8 = 0; n8 < 8; n8++) {
        acc[0][n8][0] = -ci[n8].x; acc[0][n8][1] = -ci[n8].y;
        acc[0][n8][2] = -ci[n8].x; acc[0][n8][3] = -ci[n8].y;
        acc[1][n8][0] = -ci[n8].x; acc[1][n8][1] = -ci[n8].y;
        acc[1][n8][2] = -ci[n8].x; acc[1][n8][3] = -ci[n8].y;
    }
#pragma unroll
    for (int ks = 0; ks < 4; ks++) {
        uint32_t b[8][2];
#pragma unroll
        for (int ng = 0; ng < 4; ng++) {
            if (ks >= 2 && ng < 2) continue;   // triangular: rows<32 need K<32
            uint32_t r[4];
            ldmx4(r, LbB + (ng * 16 + lr) * ROWB + ks * 32 + lc);
            b[2 * ng][0] = r[0]; b[2 * ng][1] = r[2];
            b[2 * ng + 1][0] = r[1]; b[2 * ng + 1][1] = r[3];
        }
#pragma unroll
        for (int ma = 0; ma < 2; ma++)
#pragma unroll
            for (int n8 = 0; n8 < 8; n8++) {
                if (ks >= 2 && n8 < 4) continue;
                mma16816(acc[ma][n8], afr[ks][ma], b[n8][0], b[n8][1]);
            }
    }
}

__global__ __launch_bounds__(128, 3) void main_kernel(const float* __restrict__ x,
                                                      float* __restrict__ out) {
    extern __shared__ char smem[];
    __nv_bfloat16* Xs = (__nv_bfloat16*)smem;
    float* cArea = (float*)(smem + CV_OFF);
    double* dsm = (double*)(smem + DSM_OFF);

    const int t = threadIdx.x;
    const int w = t >> 5, l = t & 31;
    const int m0w = w * 32;
    const int b0 = blockIdx.x * 128;
    uint32_t sbase = (uint32_t)__cvta_generic_to_shared(smem);
    uint32_t LbA = sbase + LB_OFF;
    uint32_t CvA = sbase + CV_OFF;
    uint32_t XsW = sbase + m0w * ROWB;
    const int lr = (l & 15);
    const int lc = (l >> 4) * 16;
    const bool own = ((l & 3) == 0);

    // ---- load X tile (128x64 f32) -> bf16 smem ----
    {
        const float4* X4 = (const float4*)(x + (size_t)b0 * 64);
#pragma unroll
        for (int q = 0; q < 16; q++) {
            int f = t + q * 128;
            int row = f >> 4, cq = f & 15;
            float4 vv = X4[f];
            __nv_bfloat162 pp0 = __float22bfloat162_rn(make_float2(vv.x, vv.y));
            __nv_bfloat162 pp1 = __float22bfloat162_rn(make_float2(vv.z, vv.w));
            uint2 pk;
            pk.x = *reinterpret_cast<uint32_t*>(&pp0);
            pk.y = *reinterpret_cast<uint32_t*>(&pp1);
            *reinterpret_cast<uint2*>(&Xs[row * 72 + cq * 4]) = pk;
        }
    }

    // ---- prologue: stage comps 0..5 into slots 0..5 ----
#pragma unroll
    for (int k = 0; k < NSLOT; k++) {
        cp_slot(LbA, CvA, k, k, t);
        asm volatile("cp.async.commit_group;");
    }

    __syncthreads();   // Xs visible

    // ---- hoist A fragments ----
    uint32_t afr[4][2][4];
#pragma unroll
    for (int ks = 0; ks < 4; ks++)
#pragma unroll
        for (int ma = 0; ma < 2; ma++)
            ldmx4(afr[ks][ma], XsW + (ma * 16 + lr) * ROWB + ks * 32 + lc);

    float acc[2][8][4];
    float runm[4], runs[4];
#pragma unroll
    for (int i = 0; i < 4; i++) { runm[i] = -INFINITY; runs[i] = 0.0f; }

    // groups of 3 comps: 2 barriers / 3 comps
    for (int g = 0; g < KC; g += 3) {
        asm volatile("cp.async.wait_group 3;");   // comps g..g+2 resident
        __syncthreads();

#pragma unroll
        for (int kk = 0; kk < 3; kk++) {
            const int k = g + kk;
            if (k >= KC) break;                    // tail guard (restored)
            const int slot = k % NSLOT;

            float2 ci[8];
            const float2* cv = (const float2*)(cArea + slot * 64);
#pragma unroll
            for (int n8 = 0; n8 < 8; n8++)
                ci[n8] = cv[n8 * 4 + (l & 3)];

            gemm_tile(acc, afr, LbA + slot * LB_BYTES, ci, lr, lc);

            float p[4];
#pragma unroll
            for (int ma = 0; ma < 2; ma++) {
                float s0 = 0.0f, s1 = 0.0f;
#pragma unroll
                for (int n8 = 0; n8 < 8; n8++) {
                    s0 = fmaf(acc[ma][n8][0], acc[ma][n8][0], s0);
                    s0 = fmaf(acc[ma][n8][1], acc[ma][n8][1], s0);
                    s1 = fmaf(acc[ma][n8][2], acc[ma][n8][2], s1);
                    s1 = fmaf(acc[ma][n8][3], acc[ma][n8][3], s1);
                }
                p[ma * 2] = s0; p[ma * 2 + 1] = s1;
            }
#pragma unroll
            for (int off = 1; off <= 2; off <<= 1)
#pragma unroll
                for (int i = 0; i < 4; i++)
                    p[i] += __shfl_xor_sync(0xffffffffu, p[i], off);

            if (own) {
                float c2 = g_const2[k];
#pragma unroll
                for (int i = 0; i < 4; i++) {
                    float s = fmaf(-0.5f, p[i], c2);
                    float nm = fmaxf(runm[i], s);
                    runs[i] = runs[i] * __expf(runm[i] - nm) + __expf(s - nm);
                    runm[i] = nm;
                }
            }
        }

        __syncthreads();   // all warps done reading slots g..g+2
#pragma unroll
        for (int kk = 0; kk < 3; kk++) {
            const int kp = g + NSLOT + kk;
            if (kp < KC) cp_slot(LbA, CvA, kp % NSLOT, kp, t);
            asm volatile("cp.async.commit_group;");
        }
    }

    // ---- per-CTA deterministic reduction ----
    double lps = 0.0;
    if (own) {
#pragma unroll
        for (int i = 0; i < 4; i++)
            lps += (double)(runm[i] + logf(runs[i]));
    }
#pragma unroll
    for (int off = 16; off > 0; off >>= 1)
        lps += __shfl_xor_sync(0xffffffffu, lps, off);
    if (l == 0) dsm[w] = lps;
    __syncthreads();
    if (t == 0)
        g_partial[blockIdx.x] = dsm[0] + dsm[1] + dsm[2] + dsm[3];

    // ---- last-block final reduction ----
    __shared__ bool isLast;
    __threadfence();
    if (t == 0) isLast = (atomicAdd(&g_cnt, 1u) == 255u);
    __syncthreads();
    if (isLast) {
        __threadfence();
        const volatile double* gp = (const volatile double*)g_partial;
        __shared__ double dd[128];
        dd[t] = gp[t] + gp[t + 128];
        __syncthreads();
        for (int s = 64; s > 0; s >>= 1) {
            if (t < s) dd[t] += dd[t + s];
            __syncthreads();
        }
        if (t == 0) out[0] = (float)(-dd[0] / (double)BTOT);
    }
}

// ============================================================
extern "C" void kernel_launch(void* const* d_in, const int* in_sizes, int n_in,
                              void* d_out, int out_size) {
    const float* x           = (const float*)d_in[0];
    const float* means_raw   = (const float*)d_in[1];
    const float* scale_raw   = (const float*)d_in[2];
    const float* weights_raw = (const float*)d_in[3];
    float* out = (float*)d_out;

    cudaFuncSetAttribute(main_kernel, cudaFuncAttributeMaxDynamicSharedMemorySize,
                         SMEM_TOTAL);

    prep_kernel<<<64, 256>>>(means_raw, scale_raw, weights_raw);
    main_kernel<<<256, 128, SMEM_TOTAL>>>(x, out);
}